// round 6
// baseline (speedup 1.0000x reference)
#include <cuda_runtime.h>
#include <cuda_fp16.h>
#include <cstdint>

#define N_NODES 50000
#define N_EDGES 600000
#define D 128

// ---------------- scratch (static device globals; no allocation) ----------
__device__ float  g_dis[N_NODES];
__device__ int    g_counts[N_NODES];
__device__ int    g_base[N_NODES];
__device__ int    g_cursor[N_NODES];
__device__ int    g_total;
__device__ int    g_csr_src[N_EDGES];
__device__ __half g_hw[(size_t)N_NODES * D];     // hw' (dis-scaled) fp16
__device__ __half g_x_hi[(size_t)N_NODES * D];   // X split hi
__device__ __half g_x_lo[(size_t)N_NODES * D];   // X split lo
__device__ __half g_a_hi[(size_t)N_NODES * D];   // act split hi
__device__ __half g_a_lo[(size_t)N_NODES * D];   // act split lo
__device__ __half g_w_hi[2][D * D];              // W^T split hi (per layer)
__device__ __half g_w_lo[2][D * D];              // W^T split lo
__device__ float  g_hw3[N_NODES];

// ---------------- helpers -------------------------------------------------
__device__ __forceinline__ void split2(float x, float y, uint32_t& hi, uint32_t& lo) {
    __half2 h = __floats2half2_rn(x, y);
    float2 hf = __half22float2(h);
    __half2 l = __floats2half2_rn(x - hf.x, y - hf.y);
    hi = *(uint32_t*)&h;
    lo = *(uint32_t*)&l;
}

// ---------------- preprocessing ------------------------------------------
__global__ void hist_kernel(const int* __restrict__ dst) {
    int i = blockIdx.x * blockDim.x + threadIdx.x;
    if (i * 4 < N_EDGES) {
        int4 d4 = *(const int4*)(dst + i * 4);
        atomicAdd(&g_counts[d4.x], 1);
        atomicAdd(&g_counts[d4.y], 1);
        atomicAdd(&g_counts[d4.z], 1);
        atomicAdd(&g_counts[d4.w], 1);
    }
}

__global__ void prefix_kernel() {
    __shared__ int sh[256];
    __shared__ int block_base;
    int i = blockIdx.x * 256 + threadIdx.x;
    int c = (i < N_NODES) ? g_counts[i] : 0;
    int v = c;
    sh[threadIdx.x] = v;
    __syncthreads();
    #pragma unroll
    for (int off = 1; off < 256; off <<= 1) {
        int t = (threadIdx.x >= off) ? sh[threadIdx.x - off] : 0;
        __syncthreads();
        v += t;
        sh[threadIdx.x] = v;
        __syncthreads();
    }
    if (threadIdx.x == 255) block_base = atomicAdd(&g_total, v);
    __syncthreads();
    if (i < N_NODES) {
        int base = block_base + v - c;
        g_base[i]   = base;
        g_cursor[i] = base;
        g_dis[i]    = rsqrtf((float)c + 1.0f);
    }
}

__global__ void scatter_kernel(const int* __restrict__ src,
                               const int* __restrict__ dst) {
    int i = blockIdx.x * blockDim.x + threadIdx.x;
    if (i * 4 < N_EDGES) {
        int4 s4 = *(const int4*)(src + i * 4);
        int4 d4 = *(const int4*)(dst + i * 4);
        int p0 = atomicAdd(&g_cursor[d4.x], 1);
        int p1 = atomicAdd(&g_cursor[d4.y], 1);
        int p2 = atomicAdd(&g_cursor[d4.z], 1);
        int p3 = atomicAdd(&g_cursor[d4.w], 1);
        g_csr_src[p0] = s4.x;
        g_csr_src[p1] = s4.y;
        g_csr_src[p2] = s4.z;
        g_csr_src[p3] = s4.w;
    }
}

// ---------------- input splitting ------------------------------------------
__global__ void split_x_kernel(const float* __restrict__ X) {
    size_t base = ((size_t)blockIdx.x * blockDim.x + threadIdx.x) * 8;
    if (base >= (size_t)N_NODES * D) return;
    float4 v0 = *(const float4*)(X + base);
    float4 v1 = *(const float4*)(X + base + 4);
    uint32_t h0, l0, h1, l1, h2, l2, h3, l3;
    split2(v0.x, v0.y, h0, l0); split2(v0.z, v0.w, h1, l1);
    split2(v1.x, v1.y, h2, l2); split2(v1.z, v1.w, h3, l3);
    *(uint4*)(g_x_hi + base) = make_uint4(h0, h1, h2, h3);
    *(uint4*)(g_x_lo + base) = make_uint4(l0, l1, l2, l3);
}

// W[k][n] (row-major) -> Wt_hi/lo[n][k]
__global__ void split_wt_kernel(const float* __restrict__ W, int layer) {
    int i = blockIdx.x * blockDim.x + threadIdx.x;
    if (i >= D * D) return;
    int n = i >> 7, k = i & 127;
    float v = W[k * D + n];
    __half h = __float2half_rn(v);
    g_w_hi[layer][i] = h;
    g_w_lo[layer][i] = __float2half_rn(v - __half2float(h));
}

// ---------------- fp16 hi/lo 3-term GEMM, cp.async 4-stage ---------------
// OUT(fp16)[r][c] = (A[M,128] @ Wt^T)[r][c] * g_dis[r]
// A given as hi/lo fp16 [node][k]; W as hi/lo fp16 [n][k] (transposed).
// block tile 128(M) x 64(N); kc chunk 16; 8 warps 4x2; warp tile 32x32.

__device__ __forceinline__ void cp16(uint32_t dst, const void* src, int sz) {
    asm volatile("cp.async.cg.shared.global [%0], [%1], 16, %2;"
                 :: "r"(dst), "l"(src), "r"(sz));
}
__device__ __forceinline__ void ldsm_x4(uint32_t& r0, uint32_t& r1, uint32_t& r2,
                                        uint32_t& r3, uint32_t addr) {
    asm volatile("ldmatrix.sync.aligned.m8n8.x4.shared.b16 {%0,%1,%2,%3}, [%4];"
                 : "=r"(r0), "=r"(r1), "=r"(r2), "=r"(r3) : "r"(addr));
}
__device__ __forceinline__ void mma_f16(float4& d, const uint32_t* a, const uint32_t* b) {
    asm volatile(
        "mma.sync.aligned.m16n8k16.row.col.f32.f16.f16.f32 "
        "{%0,%1,%2,%3}, {%4,%5,%6,%7}, {%8,%9}, {%0,%1,%2,%3};"
        : "+f"(d.x), "+f"(d.y), "+f"(d.z), "+f"(d.w)
        : "r"(a[0]), "r"(a[1]), "r"(a[2]), "r"(a[3]), "r"(b[0]), "r"(b[1]));
}

// stage layout (bytes): Ah[128 rows x 48B pitch] = 6144, Al = 6144,
//                       Bh[64 x 48] = 3072, Bl = 3072  -> 18432 per stage
#define STAGE_BYTES 18432
#define A_LO_OFF    6144
#define B_BASE      12288
#define B_LO_OFF    3072
#define GEMM_SMEM   (4 * STAGE_BYTES)

__global__ __launch_bounds__(256, 2)
void gemm_f16_cp(const __half* __restrict__ Ah, const __half* __restrict__ Al,
                 const __half* __restrict__ Bh, const __half* __restrict__ Bl,
                 __half* __restrict__ OUT, int M) {
    extern __shared__ __align__(16) char smem[];
    uint32_t sm = (uint32_t)__cvta_generic_to_shared(smem);

    int tid = threadIdx.x;
    int wid = tid >> 5, lane = tid & 31;
    int wm = wid >> 1, wn = wid & 1;
    int g = lane >> 2, t = lane & 3;
    int block_row = blockIdx.x * 128;
    int n0 = blockIdx.y * 64;

    // cp.async coordinates: A -> 2 ops/thread (hi+lo), B -> 1 op/thread
    int a_r = tid >> 1, a_h = tid & 1;
    int gr = block_row + a_r;
    int a_sz = (gr < M) ? 16 : 0;
    const __half* srcAh = Ah + (size_t)gr * D + a_h * 8;
    const __half* srcAl = Al + (size_t)gr * D + a_h * 8;
    int b_n = tid >> 2, b_q = tid & 3;
    int b_buf = b_q >> 1, b_h = b_q & 1;
    const __half* srcB = (b_buf ? Bl : Bh) + (size_t)(n0 + b_n) * D + b_h * 8;
    uint32_t dA = (uint32_t)(a_r * 48 + a_h * 16);
    uint32_t dB = (uint32_t)(B_BASE + b_buf * B_LO_OFF + b_n * 48 + b_h * 16);

    // ldmatrix per-lane offsets (relative to stage base)
    uint32_t a_off, b_off;
    {
        int arow = wm * 32 + (lane & 7) + ((lane >> 3) & 1) * 8;
        int abyte = ((lane >> 4) & 1) * 16;
        a_off = arow * 48 + abyte;
        int m = lane >> 3;
        int nrow = wn * 32 + (m >> 1) * 8 + (lane & 7);
        int kb = (m & 1) * 16;
        b_off = B_BASE + nrow * 48 + kb;
    }

    float4 acc[2][4];
    #pragma unroll
    for (int mt = 0; mt < 2; mt++)
        #pragma unroll
        for (int nt = 0; nt < 4; nt++)
            acc[mt][nt] = make_float4(0.f, 0.f, 0.f, 0.f);

    // issue copy for k-chunk c into stage c&3
    #define ISSUE_CHUNK(c)                                                    \
    {                                                                         \
        uint32_t sb = sm + ((c) & 3) * STAGE_BYTES;                           \
        cp16(sb + dA,            srcAh + (c) * 16, a_sz);                     \
        cp16(sb + A_LO_OFF + dA, srcAl + (c) * 16, a_sz);                     \
        cp16(sb + dB,            srcB  + (c) * 16, 16);                       \
        asm volatile("cp.async.commit_group;");                               \
    }

    ISSUE_CHUNK(0);
    ISSUE_CHUNK(1);
    ISSUE_CHUNK(2);

    #pragma unroll
    for (int it = 0; it < 8; it++) {
        asm volatile("cp.async.wait_group 2;");
        __syncthreads();

        uint32_t base = sm + (it & 3) * STAGE_BYTES;
        uint32_t a_ld = base + a_off;
        uint32_t b_ld = base + b_off;

        uint32_t ah[2][4], al[2][4], bh[4][2], bl[4][2];
        ldsm_x4(ah[0][0], ah[0][1], ah[0][2], ah[0][3], a_ld);
        ldsm_x4(ah[1][0], ah[1][1], ah[1][2], ah[1][3], a_ld + 768);
        ldsm_x4(al[0][0], al[0][1], al[0][2], al[0][3], a_ld + A_LO_OFF);
        ldsm_x4(al[1][0], al[1][1], al[1][2], al[1][3], a_ld + A_LO_OFF + 768);
        ldsm_x4(bh[0][0], bh[0][1], bh[1][0], bh[1][1], b_ld);
        ldsm_x4(bh[2][0], bh[2][1], bh[3][0], bh[3][1], b_ld + 768);
        ldsm_x4(bl[0][0], bl[0][1], bl[1][0], bl[1][1], b_ld + B_LO_OFF);
        ldsm_x4(bl[2][0], bl[2][1], bl[3][0], bl[3][1], b_ld + B_LO_OFF + 768);

        // prefetch chunk it+3 (buffer (it-1)&3: fully consumed — every warp
        // passed this iteration's barrier only after its it-1 ldmatrix)
        if (it < 5) {
            ISSUE_CHUNK(it + 3);
        } else {
            asm volatile("cp.async.commit_group;");   // keep group count uniform
        }

        #pragma unroll
        for (int mt = 0; mt < 2; mt++)
            #pragma unroll
            for (int nt = 0; nt < 4; nt++) {
                mma_f16(acc[mt][nt], ah[mt], bh[nt]);
                mma_f16(acc[mt][nt], ah[mt], bl[nt]);
                mma_f16(acc[mt][nt], al[mt], bh[nt]);
            }
    }

    // epilogue: scale rows by dis, store fp16
    #pragma unroll
    for (int mt = 0; mt < 2; mt++) {
        int r0 = block_row + wm * 32 + mt * 16 + g;
        int r1 = r0 + 8;
        float d0 = (r0 < M) ? g_dis[r0] : 0.f;
        float d1 = (r1 < M) ? g_dis[r1] : 0.f;
        #pragma unroll
        for (int nt = 0; nt < 4; nt++) {
            int col = n0 + wn * 32 + nt * 8 + 2 * t;
            float4 c = acc[mt][nt];
            if (r0 < M)
                *(__half2*)(OUT + (size_t)r0 * D + col) = __floats2half2_rn(c.x * d0, c.y * d0);
            if (r1 < M)
                *(__half2*)(OUT + (size_t)r1 * D + col) = __floats2half2_rn(c.z * d1, c.w * d1);
        }
    }
}

// ---------------- aggregation (warp per node), F=128, fp16 gathers --------
// !FUSE: act written as hi/lo fp16 pair (next GEMM's A input)
// FUSE:  g_hw3[node] = dot(act, W3) * dis[node]
template <bool FUSE_GEMV>
__global__ __launch_bounds__(256)
void agg128_kernel(const __half* __restrict__ HW, const float* __restrict__ bias,
                   __half* __restrict__ OUTh, __half* __restrict__ OUTl,
                   const float* __restrict__ W3) {
    int warp = (blockIdx.x * blockDim.x + threadIdx.x) >> 5;
    int lane = threadIdx.x & 31;
    if (warp >= N_NODES) return;
    int node = warp;

    const uint2* rowp = (const uint2*)(HW + (size_t)node * D) + lane;
    uint2 sv = *rowp;
    float2 a0 = __half22float2(*(const __half2*)&sv.x);
    float2 a1 = __half22float2(*(const __half2*)&sv.y);
    float4 acc = make_float4(a0.x, a0.y, a1.x, a1.y);

    int beg = g_base[node];
    int end = beg + g_counts[node];
    int e = beg;
    for (; e + 2 <= end; e += 2) {
        int s0 = __ldg(&g_csr_src[e]);
        int s1 = __ldg(&g_csr_src[e + 1]);
        uint2 v0 = *((const uint2*)(HW + (size_t)s0 * D) + lane);
        uint2 v1 = *((const uint2*)(HW + (size_t)s1 * D) + lane);
        float2 f00 = __half22float2(*(const __half2*)&v0.x);
        float2 f01 = __half22float2(*(const __half2*)&v0.y);
        float2 f10 = __half22float2(*(const __half2*)&v1.x);
        float2 f11 = __half22float2(*(const __half2*)&v1.y);
        acc.x += f00.x + f10.x; acc.y += f00.y + f10.y;
        acc.z += f01.x + f11.x; acc.w += f01.y + f11.y;
    }
    if (e < end) {
        int s = __ldg(&g_csr_src[e]);
        uint2 v = *((const uint2*)(HW + (size_t)s * D) + lane);
        float2 f0 = __half22float2(*(const __half2*)&v.x);
        float2 f1 = __half22float2(*(const __half2*)&v.y);
        acc.x += f0.x; acc.y += f0.y; acc.z += f1.x; acc.w += f1.y;
    }

    float dn = g_dis[node];
    float4 b = ((const float4*)bias)[lane];
    acc.x = fmaxf(acc.x * dn + b.x, 0.f);
    acc.y = fmaxf(acc.y * dn + b.y, 0.f);
    acc.z = fmaxf(acc.z * dn + b.z, 0.f);
    acc.w = fmaxf(acc.w * dn + b.w, 0.f);

    if (FUSE_GEMV) {
        float4 w = ((const float4*)W3)[lane];
        float dot = acc.x * w.x + acc.y * w.y + acc.z * w.z + acc.w * w.w;
        #pragma unroll
        for (int off = 16; off > 0; off >>= 1)
            dot += __shfl_down_sync(0xFFFFFFFFu, dot, off);
        if (lane == 0) g_hw3[node] = dot * dn;
    } else {
        uint32_t h01, l01, h23, l23;
        split2(acc.x, acc.y, h01, l01);
        split2(acc.z, acc.w, h23, l23);
        ((uint2*)(OUTh + (size_t)node * D))[lane] = make_uint2(h01, h23);
        ((uint2*)(OUTl + (size_t)node * D))[lane] = make_uint2(l01, l23);
    }
}

// ---------------- layer 3: scalar aggregation -----------------------------
__global__ void agg3_kernel(const float* __restrict__ b3, float* __restrict__ OUT) {
    int node = blockIdx.x * blockDim.x + threadIdx.x;
    if (node >= N_NODES) return;
    float acc = g_hw3[node];
    int beg = g_base[node];
    int end = beg + g_counts[node];
    for (int e = beg; e < end; e++)
        acc += g_hw3[__ldg(&g_csr_src[e])];
    OUT[node] = fmaxf(acc * g_dis[node] + b3[0], 0.f);
}

// ---------------- launch ---------------------------------------------------
extern "C" void kernel_launch(void* const* d_in, const int* in_sizes, int n_in,
                              void* d_out, int out_size) {
    const float* x  = (const float*)d_in[0];
    const int*   ei = (const int*)d_in[1];
    const float* W1 = (const float*)d_in[2];
    const float* b1 = (const float*)d_in[3];
    const float* W2 = (const float*)d_in[4];
    const float* b2 = (const float*)d_in[5];
    const float* W3 = (const float*)d_in[6];
    const float* b3 = (const float*)d_in[7];
    float* out = (float*)d_out;

    const int* src = ei;
    const int* dst = ei + N_EDGES;

    __half *hw, *xh, *xl, *ah, *al, *wh, *wl;
    cudaGetSymbolAddress((void**)&hw, g_hw);
    cudaGetSymbolAddress((void**)&xh, g_x_hi);
    cudaGetSymbolAddress((void**)&xl, g_x_lo);
    cudaGetSymbolAddress((void**)&ah, g_a_hi);
    cudaGetSymbolAddress((void**)&al, g_a_lo);
    cudaGetSymbolAddress((void**)&wh, g_w_hi);
    cudaGetSymbolAddress((void**)&wl, g_w_lo);
    int* counts; cudaGetSymbolAddress((void**)&counts, g_counts);
    int* total;  cudaGetSymbolAddress((void**)&total,  g_total);

    static bool attr_set = false;
    if (!attr_set) {
        cudaFuncSetAttribute(gemm_f16_cp,
                             cudaFuncAttributeMaxDynamicSharedMemorySize, GEMM_SMEM);
        attr_set = true;
    }

    int nb_nodes = (N_NODES + 255) / 256;
    int nb_edge4 = (N_EDGES / 4 + 255) / 256;
    int nb_warp  = (N_NODES * 32 + 255) / 256;
    int nb_split = ((N_NODES * D / 8) + 255) / 256;
    dim3 gemm_grid((N_NODES + 127) / 128, 2);

    // preprocessing: unordered CSR by dst
    cudaMemsetAsync(counts, 0, N_NODES * sizeof(int));
    cudaMemsetAsync(total, 0, sizeof(int));
    hist_kernel<<<nb_edge4, 256>>>(dst);
    prefix_kernel<<<nb_nodes, 256>>>();
    scatter_kernel<<<nb_edge4, 256>>>(src, dst);

    // input splitting
    split_x_kernel<<<nb_split, 256>>>(x);
    split_wt_kernel<<<(D * D + 255) / 256, 256>>>(W1, 0);
    split_wt_kernel<<<(D * D + 255) / 256, 256>>>(W2, 1);

    // layer 1
    gemm_f16_cp<<<gemm_grid, 256, GEMM_SMEM>>>(xh, xl, wh, wl, hw, N_NODES);
    agg128_kernel<false><<<nb_warp, 256>>>(hw, b1, ah, al, nullptr);
    // layer 2 (+ fused layer-3 GEMV)
    gemm_f16_cp<<<gemm_grid, 256, GEMM_SMEM>>>(ah, al, wh + D * D, wl + D * D, hw, N_NODES);
    agg128_kernel<true><<<nb_warp, 256>>>(hw, b2, nullptr, nullptr, W3);
    // layer 3 aggregation
    agg3_kernel<<<nb_nodes, 256>>>(b3, out);
}

// round 7
// speedup vs baseline: 1.2294x; 1.2294x over previous
#include <cuda_runtime.h>
#include <cuda_fp16.h>
#include <cstdint>

#define N_NODES 50000
#define N_EDGES 600000
#define D 128

// ---------------- scratch (static device globals; no allocation) ----------
__device__ float  g_dis[N_NODES];
__device__ int    g_counts[N_NODES];
__device__ int    g_base[N_NODES];
__device__ int    g_cursor[N_NODES];
__device__ int    g_total;
__device__ int    g_csr_src[N_EDGES];
__device__ __half g_hw[(size_t)N_NODES * D];     // hw' (dis-scaled) fp16
__device__ __half g_acth[(size_t)N_NODES * D];   // activation fp16
__device__ float  g_hw3[N_NODES];

// ---------------- preprocessing ------------------------------------------
__global__ void hist_kernel(const int* __restrict__ dst) {
    int i = blockIdx.x * blockDim.x + threadIdx.x;
    if (i * 4 < N_EDGES) {
        int4 d4 = *(const int4*)(dst + i * 4);
        atomicAdd(&g_counts[d4.x], 1);
        atomicAdd(&g_counts[d4.y], 1);
        atomicAdd(&g_counts[d4.z], 1);
        atomicAdd(&g_counts[d4.w], 1);
    }
}

__global__ void prefix_kernel() {
    __shared__ int sh[256];
    __shared__ int block_base;
    int i = blockIdx.x * 256 + threadIdx.x;
    int c = (i < N_NODES) ? g_counts[i] : 0;
    int v = c;
    sh[threadIdx.x] = v;
    __syncthreads();
    #pragma unroll
    for (int off = 1; off < 256; off <<= 1) {
        int t = (threadIdx.x >= off) ? sh[threadIdx.x - off] : 0;
        __syncthreads();
        v += t;
        sh[threadIdx.x] = v;
        __syncthreads();
    }
    if (threadIdx.x == 255) block_base = atomicAdd(&g_total, v);
    __syncthreads();
    if (i < N_NODES) {
        int base = block_base + v - c;
        g_base[i]   = base;
        g_cursor[i] = base;
        g_dis[i]    = rsqrtf((float)c + 1.0f);
    }
}

__global__ void scatter_kernel(const int* __restrict__ src,
                               const int* __restrict__ dst) {
    int i = blockIdx.x * blockDim.x + threadIdx.x;
    if (i * 4 < N_EDGES) {
        int4 s4 = *(const int4*)(src + i * 4);
        int4 d4 = *(const int4*)(dst + i * 4);
        int p0 = atomicAdd(&g_cursor[d4.x], 1);
        int p1 = atomicAdd(&g_cursor[d4.y], 1);
        int p2 = atomicAdd(&g_cursor[d4.z], 1);
        int p3 = atomicAdd(&g_cursor[d4.w], 1);
        g_csr_src[p0] = s4.x;
        g_csr_src[p1] = s4.y;
        g_csr_src[p2] = s4.z;
        g_csr_src[p3] = s4.w;
    }
}

// ---------------- 2-term fp16 GEMM (A fp16, W split hi/lo) ---------------
// OUT(fp16)[r][c] = (A[M,128] @ W[128,128])[r][c] * g_dis[r]
// D = A*Wh + A*Wl. A error ~2.8e-4 rms; W error corrected (~2^-22).
// block tile 128(M) x 64(N); kc chunk 16; 8 warps 4x2; warp tile 32x32.

__device__ __forceinline__ void split2(float x, float y, uint32_t& hi, uint32_t& lo) {
    __half2 h = __floats2half2_rn(x, y);
    float2 hf = __half22float2(h);
    __half2 l = __floats2half2_rn(x - hf.x, y - hf.y);
    hi = *(uint32_t*)&h;
    lo = *(uint32_t*)&l;
}

__device__ __forceinline__ void ldsm_x4(uint32_t& r0, uint32_t& r1, uint32_t& r2,
                                        uint32_t& r3, uint32_t addr) {
    asm volatile("ldmatrix.sync.aligned.m8n8.x4.shared.b16 {%0,%1,%2,%3}, [%4];"
                 : "=r"(r0), "=r"(r1), "=r"(r2), "=r"(r3) : "r"(addr));
}

__device__ __forceinline__ void mma_f16(float4& d, const uint32_t* a, const uint32_t* b) {
    asm volatile(
        "mma.sync.aligned.m16n8k16.row.col.f32.f16.f16.f32 "
        "{%0,%1,%2,%3}, {%4,%5,%6,%7}, {%8,%9}, {%0,%1,%2,%3};"
        : "+f"(d.x), "+f"(d.y), "+f"(d.z), "+f"(d.w)
        : "r"(a[0]), "r"(a[1]), "r"(a[2]), "r"(a[3]), "r"(b[0]), "r"(b[1]));
}

// smem (bytes): A hi [128 rows x 48B pitch] = 6144; B at 6144:
//   hi rows n=0..63, lo rows 64..127, 48B pitch = 6144. Total 12288 B.
#define B_BASE   6144
#define B_LO_OFF 3072

template <bool A_F16>
__global__ __launch_bounds__(256, 2)
void gemm_2t(const float* __restrict__ Xf, const __half* __restrict__ Xh,
             const float* __restrict__ W, __half* __restrict__ OUT, int M) {
    __shared__ __align__(16) char smem[12288];
    uint32_t sm = (uint32_t)__cvta_generic_to_shared(smem);

    int tid = threadIdx.x;
    int wid = tid >> 5, lane = tid & 31;
    int wm = wid >> 1, wn = wid & 1;         // 4 x 2 warp grid
    int g = lane >> 2, t = lane & 3;
    int block_row = blockIdx.x * 128;
    int n0 = blockIdx.y * 64;

    // ---- A load coordinates ----
    // fp32 path: 2 rows per thread (a_r0, a_r0+64), 4 floats each
    int a_r0 = tid >> 2;
    int a_c4 = (tid & 3) * 4;
    // fp16 path: 1 half-row per thread (8 halves)
    int a_r16 = tid >> 1;
    int a_h16 = tid & 1;

    int gr0, gr1;
    const float*  Xp0 = nullptr; const float* Xp1 = nullptr;
    const __half* Xph = nullptr;
    uint32_t a_st0 = 0, a_st1 = 0, a_st16 = 0;
    if (A_F16) {
        gr0 = block_row + a_r16; gr1 = 0;
        Xph = Xh + (size_t)gr0 * D + a_h16 * 8;
        a_st16 = sm + a_r16 * 48 + a_h16 * 16;
    } else {
        gr0 = block_row + a_r0; gr1 = gr0 + 64;
        Xp0 = Xf + (size_t)gr0 * D + a_c4;
        Xp1 = Xf + (size_t)gr1 * D + a_c4;
        a_st0 = sm + a_r0 * 48 + a_c4 * 2;
        a_st1 = sm + (a_r0 + 64) * 48 + a_c4 * 2;
    }

    // ---- B load coordinates (W fp32 row-major [k][n]) ----
    int b_n  = tid & 63;
    int b_k0 = (tid >> 6) * 4;
    const float* Wp = W + (size_t)b_k0 * D + n0 + b_n;
    uint32_t b_st = sm + B_BASE + b_n * 48 + b_k0 * 2;

    // ---- ldmatrix per-lane addresses ----
    uint32_t a_ld, b_ld;
    {
        int arow = wm * 32 + (lane & 7) + ((lane >> 3) & 1) * 8;
        int abyte = ((lane >> 4) & 1) * 16;
        a_ld = sm + arow * 48 + abyte;
        int m = lane >> 3;
        int nrow = wn * 32 + (m >> 1) * 8 + (lane & 7);
        int kb = (m & 1) * 16;
        b_ld = sm + B_BASE + nrow * 48 + kb;
    }

    float4 acc[2][4];
    #pragma unroll
    for (int mt = 0; mt < 2; mt++)
        #pragma unroll
        for (int nt = 0; nt < 4; nt++)
            acc[mt][nt] = make_float4(0.f, 0.f, 0.f, 0.f);

    // prologue: load chunk 0 into registers
    float4 vA0, vA1; uint4 vAh;
    if (A_F16) {
        vAh = (gr0 < M) ? *(const uint4*)Xph : make_uint4(0, 0, 0, 0);
    } else {
        vA0 = (gr0 < M) ? *(const float4*)Xp0 : make_float4(0.f, 0.f, 0.f, 0.f);
        vA1 = (gr1 < M) ? *(const float4*)Xp1 : make_float4(0.f, 0.f, 0.f, 0.f);
    }
    float w0 = Wp[0], w1 = Wp[D], w2 = Wp[2 * D], w3 = Wp[3 * D];

    #pragma unroll
    for (int it = 0; it < 8; it++) {
        // stage current chunk to smem
        if (A_F16) {
            asm volatile("st.shared.v4.b32 [%0], {%1,%2,%3,%4};"
                         :: "r"(a_st16), "r"(vAh.x), "r"(vAh.y), "r"(vAh.z), "r"(vAh.w));
        } else {
            __half2 h01 = __floats2half2_rn(vA0.x, vA0.y);
            __half2 h23 = __floats2half2_rn(vA0.z, vA0.w);
            asm volatile("st.shared.v2.b32 [%0], {%1,%2};"
                         :: "r"(a_st0), "r"(*(uint32_t*)&h01), "r"(*(uint32_t*)&h23));
            h01 = __floats2half2_rn(vA1.x, vA1.y);
            h23 = __floats2half2_rn(vA1.z, vA1.w);
            asm volatile("st.shared.v2.b32 [%0], {%1,%2};"
                         :: "r"(a_st1), "r"(*(uint32_t*)&h01), "r"(*(uint32_t*)&h23));
        }
        {
            uint32_t h01, l01, h23, l23;
            split2(w0, w1, h01, l01);
            split2(w2, w3, h23, l23);
            asm volatile("st.shared.v2.b32 [%0], {%1,%2};" :: "r"(b_st), "r"(h01), "r"(h23));
            asm volatile("st.shared.v2.b32 [%0], {%1,%2};" :: "r"(b_st + B_LO_OFF), "r"(l01), "r"(l23));
        }
        __syncthreads();

        // prefetch next chunk (overlaps MMA block below)
        if (it < 7) {
            int kc = (it + 1) * 16;
            if (A_F16) {
                vAh = (gr0 < M) ? *(const uint4*)(Xph + kc) : make_uint4(0, 0, 0, 0);
            } else {
                vA0 = (gr0 < M) ? *(const float4*)(Xp0 + kc) : make_float4(0.f, 0.f, 0.f, 0.f);
                vA1 = (gr1 < M) ? *(const float4*)(Xp1 + kc) : make_float4(0.f, 0.f, 0.f, 0.f);
            }
            const float* wp = Wp + (size_t)kc * D;
            w0 = wp[0]; w1 = wp[D]; w2 = wp[2 * D]; w3 = wp[3 * D];
        }

        // fragments
        uint32_t ah[2][4], bh[4][2], bl[4][2];
        ldsm_x4(ah[0][0], ah[0][1], ah[0][2], ah[0][3], a_ld);
        ldsm_x4(ah[1][0], ah[1][1], ah[1][2], ah[1][3], a_ld + 768);
        ldsm_x4(bh[0][0], bh[0][1], bh[1][0], bh[1][1], b_ld);
        ldsm_x4(bh[2][0], bh[2][1], bh[3][0], bh[3][1], b_ld + 768);
        ldsm_x4(bl[0][0], bl[0][1], bl[1][0], bl[1][1], b_ld + B_LO_OFF);
        ldsm_x4(bl[2][0], bl[2][1], bl[3][0], bl[3][1], b_ld + B_LO_OFF + 768);

        // hh pass then hl pass: adjacent MMAs hit different accumulators
        #pragma unroll
        for (int mt = 0; mt < 2; mt++)
            #pragma unroll
            for (int nt = 0; nt < 4; nt++)
                mma_f16(acc[mt][nt], ah[mt], bh[nt]);
        #pragma unroll
        for (int mt = 0; mt < 2; mt++)
            #pragma unroll
            for (int nt = 0; nt < 4; nt++)
                mma_f16(acc[mt][nt], ah[mt], bl[nt]);
        __syncthreads();
    }

    // epilogue: scale rows by dis, store fp16
    #pragma unroll
    for (int mt = 0; mt < 2; mt++) {
        int r0 = block_row + wm * 32 + mt * 16 + g;
        int r1 = r0 + 8;
        float d0 = (r0 < M) ? g_dis[r0] : 0.f;
        float d1 = (r1 < M) ? g_dis[r1] : 0.f;
        #pragma unroll
        for (int nt = 0; nt < 4; nt++) {
            int col = n0 + wn * 32 + nt * 8 + 2 * t;
            float4 c = acc[mt][nt];
            if (r0 < M)
                *(__half2*)(OUT + (size_t)r0 * D + col) = __floats2half2_rn(c.x * d0, c.y * d0);
            if (r1 < M)
                *(__half2*)(OUT + (size_t)r1 * D + col) = __floats2half2_rn(c.z * d1, c.w * d1);
        }
    }
}

// ---------------- aggregation (warp per node), F=128, fp16 gathers --------
// !FUSE: act written as fp16 (next GEMM's A input)
// FUSE:  g_hw3[node] = dot(act, W3) * dis[node]
template <bool FUSE_GEMV>
__global__ __launch_bounds__(256)
void agg128_kernel(const __half* __restrict__ HW, const float* __restrict__ bias,
                   __half* __restrict__ OUTH, const float* __restrict__ W3) {
    int warp = (blockIdx.x * blockDim.x + threadIdx.x) >> 5;
    int lane = threadIdx.x & 31;
    if (warp >= N_NODES) return;
    int node = warp;

    const uint2* rowp = (const uint2*)(HW + (size_t)node * D) + lane;
    uint2 sv = *rowp;
    float2 a0 = __half22float2(*(const __half2*)&sv.x);
    float2 a1 = __half22float2(*(const __half2*)&sv.y);
    float4 acc = make_float4(a0.x, a0.y, a1.x, a1.y);

    int beg = g_base[node];
    int end = beg + g_counts[node];
    int e = beg;
    for (; e + 2 <= end; e += 2) {
        int s0 = __ldg(&g_csr_src[e]);
        int s1 = __ldg(&g_csr_src[e + 1]);
        uint2 v0 = *((const uint2*)(HW + (size_t)s0 * D) + lane);
        uint2 v1 = *((const uint2*)(HW + (size_t)s1 * D) + lane);
        float2 f00 = __half22float2(*(const __half2*)&v0.x);
        float2 f01 = __half22float2(*(const __half2*)&v0.y);
        float2 f10 = __half22float2(*(const __half2*)&v1.x);
        float2 f11 = __half22float2(*(const __half2*)&v1.y);
        acc.x += f00.x + f10.x; acc.y += f00.y + f10.y;
        acc.z += f01.x + f11.x; acc.w += f01.y + f11.y;
    }
    if (e < end) {
        int s = __ldg(&g_csr_src[e]);
        uint2 v = *((const uint2*)(HW + (size_t)s * D) + lane);
        float2 f0 = __half22float2(*(const __half2*)&v.x);
        float2 f1 = __half22float2(*(const __half2*)&v.y);
        acc.x += f0.x; acc.y += f0.y; acc.z += f1.x; acc.w += f1.y;
    }

    float dn = g_dis[node];
    float4 b = ((const float4*)bias)[lane];
    acc.x = fmaxf(acc.x * dn + b.x, 0.f);
    acc.y = fmaxf(acc.y * dn + b.y, 0.f);
    acc.z = fmaxf(acc.z * dn + b.z, 0.f);
    acc.w = fmaxf(acc.w * dn + b.w, 0.f);

    if (FUSE_GEMV) {
        float4 w = ((const float4*)W3)[lane];
        float dot = acc.x * w.x + acc.y * w.y + acc.z * w.z + acc.w * w.w;
        #pragma unroll
        for (int off = 16; off > 0; off >>= 1)
            dot += __shfl_down_sync(0xFFFFFFFFu, dot, off);
        if (lane == 0) g_hw3[node] = dot * dn;
    } else {
        __half2 h01 = __floats2half2_rn(acc.x, acc.y);
        __half2 h23 = __floats2half2_rn(acc.z, acc.w);
        ((uint2*)(OUTH + (size_t)node * D))[lane] =
            make_uint2(*(uint32_t*)&h01, *(uint32_t*)&h23);
    }
}

// ---------------- layer 3: scalar aggregation -----------------------------
__global__ void agg3_kernel(const float* __restrict__ b3, float* __restrict__ OUT) {
    int node = blockIdx.x * blockDim.x + threadIdx.x;
    if (node >= N_NODES) return;
    float acc = g_hw3[node];
    int beg = g_base[node];
    int end = beg + g_counts[node];
    for (int e = beg; e < end; e++)
        acc += g_hw3[__ldg(&g_csr_src[e])];
    OUT[node] = fmaxf(acc * g_dis[node] + b3[0], 0.f);
}

// ---------------- launch ---------------------------------------------------
extern "C" void kernel_launch(void* const* d_in, const int* in_sizes, int n_in,
                              void* d_out, int out_size) {
    const float* x  = (const float*)d_in[0];
    const int*   ei = (const int*)d_in[1];
    const float* W1 = (const float*)d_in[2];
    const float* b1 = (const float*)d_in[3];
    const float* W2 = (const float*)d_in[4];
    const float* b2 = (const float*)d_in[5];
    const float* W3 = (const float*)d_in[6];
    const float* b3 = (const float*)d_in[7];
    float* out = (float*)d_out;

    const int* src = ei;
    const int* dst = ei + N_EDGES;

    __half *hw, *acth;
    cudaGetSymbolAddress((void**)&hw,   g_hw);
    cudaGetSymbolAddress((void**)&acth, g_acth);
    int* counts; cudaGetSymbolAddress((void**)&counts, g_counts);
    int* total;  cudaGetSymbolAddress((void**)&total,  g_total);

    int nb_nodes = (N_NODES + 255) / 256;
    int nb_edge4 = (N_EDGES / 4 + 255) / 256;
    int nb_warp  = (N_NODES * 32 + 255) / 256;
    dim3 gemm_grid((N_NODES + 127) / 128, 2);

    // preprocessing: unordered CSR by dst
    cudaMemsetAsync(counts, 0, N_NODES * sizeof(int));
    cudaMemsetAsync(total, 0, sizeof(int));
    hist_kernel<<<nb_edge4, 256>>>(dst);
    prefix_kernel<<<nb_nodes, 256>>>();
    scatter_kernel<<<nb_edge4, 256>>>(src, dst);

    // layer 1 (A = x fp32, converted inline)
    gemm_2t<false><<<gemm_grid, 256>>>(x, nullptr, W1, hw, N_NODES);
    agg128_kernel<false><<<nb_warp, 256>>>(hw, b1, acth, nullptr);
    // layer 2 (A = act fp16 direct) + fused layer-3 GEMV
    gemm_2t<true><<<gemm_grid, 256>>>(nullptr, acth, W2, hw, N_NODES);
    agg128_kernel<true><<<nb_warp, 256>>>(hw, b2, nullptr, W3);
    // layer 3 aggregation
    agg3_kernel<<<nb_nodes, 256>>>(b3, out);
}